// round 17
// baseline (speedup 1.0000x reference)
#include <cuda_runtime.h>
#include <cuda_fp16.h>
#include <cuda_bf16.h>
#include <math.h>
#include <stdint.h>

// Problem dims
#define BATCH 2048
#define TT    128
#define VV    256
#define CC    32
#define HH    128
#define EE    256
#define GG    384   // 3*H
#define OO    256
#define NLN   3
#define BNK   32

// GRU tiling: 512 threads (16 warps x 24 gate-cols), 2 streams x 16 rows.
#define BM    32
#define NTH   512
// SMEM byte offsets
#define SW0   0                         // w fp16 [384][128], swizzled (96KB)
#define SHB(s, b) (98304 + ((s) * 2 + (b)) * 4096)  // h fp16 per stream/phase
#define SMEM_TOTAL 114688

// Head SMEM: phase A = down_w fp32 (96KB) | up_wT fp32 (96KB); y hi/lo 16KB.
#define HDOWN 0
#define HUP   98304
#define HYHI  196608
#define HYLO  204800
#define HEAD_SMEM 212992

// Scratch (static device globals)
__device__ __align__(16) __half g_w0[2 * GG * HH];  // [dir][p][k] fp16 (r,z x0.5)
__device__ float g_xtab[2 * VV * GG];   // permuted x@w_ih^T + biases (r,z x0.5)
__device__ float g_feat[BATCH * EE];
__device__ float g_upwT[NLN * BNK * EE]; // up_w transposed: [l][d][e]
__device__ int   g_tokT[TT * BATCH];     // tokens transposed [t][b]
__device__ __align__(16) __half g_pw16[OO * EE];  // proj_w fp16, swizzled rows

// ---------------------------------------------------------------------------
// Activations: n-tanh via direct exp identity (2 MUFU).
// ---------------------------------------------------------------------------
__device__ __forceinline__ float tanh_e(float v) {
    float t = fminf(v * 2.8853900817779268f, 126.0f);
    float e; asm("ex2.approx.f32 %0, %1;" : "=f"(e) : "f"(t));
    float rp; asm("rcp.approx.f32 %0, %1;" : "=f"(rp) : "f"(e + 1.0f));
    return (e - 1.0f) * rp;
}

// ---------------------------------------------------------------------------
// MMA / ldmatrix wrappers
// ---------------------------------------------------------------------------
__device__ __forceinline__ void ldsm4(uint32_t& r0, uint32_t& r1, uint32_t& r2,
                                      uint32_t& r3, uint32_t addr) {
    asm volatile("ldmatrix.sync.aligned.m8n8.x4.shared.b16 {%0,%1,%2,%3}, [%4];"
                 : "=r"(r0), "=r"(r1), "=r"(r2), "=r"(r3) : "r"(addr));
}
__device__ __forceinline__ void mma16816(float* d, const uint32_t* a,
                                         uint32_t b0, uint32_t b1) {
    asm volatile(
        "mma.sync.aligned.m16n8k16.row.col.f32.f16.f16.f32 "
        "{%0,%1,%2,%3}, {%4,%5,%6,%7}, {%8,%9}, {%0,%1,%2,%3};"
        : "+f"(d[0]), "+f"(d[1]), "+f"(d[2]), "+f"(d[3])
        : "r"(a[0]), "r"(a[1]), "r"(a[2]), "r"(a[3]), "r"(b0), "r"(b1));
}

// gate-dim permutation for 16 warps (24 cols each):
// orig g = t*128 + j -> p = 24*(j>>3) + 8*t + (j&7)
__device__ __forceinline__ int permute_g(int g) {
    int t = g >> 7, j = g & 127;
    return 24 * (j >> 3) + 8 * t + (j & 7);
}

// ---------------------------------------------------------------------------
// Prep A: xtab (permuted), 4 vocab rows per CTA. b_ih + b_hh(r,z) folded;
// r,z entries x0.5 (sigmoid(x) = 0.5*tanh(x/2)+0.5 with /2 pre-applied).
// ---------------------------------------------------------------------------
__global__ void xtab_kernel(const float* __restrict__ ce,
                            const float* __restrict__ wih_f, const float* __restrict__ bih_f,
                            const float* __restrict__ wih_b, const float* __restrict__ bih_b,
                            const float* __restrict__ bhh_f, const float* __restrict__ bhh_b) {
    extern __shared__ float xsm[];
    float* ws = xsm;               // [384*32]
    float* bs = ws + GG * CC;      // [384]
    float* cs = bs + GG;           // [4*32]
    const int d = blockIdx.y, g = threadIdx.x;
    const float* wih = d ? wih_b : wih_f;
    const float* bih = d ? bih_b : bih_f;
    const float* bhh = d ? bhh_b : bhh_f;
    for (int i = g; i < GG * CC; i += GG) ws[i] = wih[i];
    bs[g] = bih[g] + (g < 2 * HH ? bhh[g] : 0.0f);
    const int v0 = blockIdx.x * 4;
    for (int i = g; i < 4 * CC; i += GG) cs[i] = ce[v0 * CC + i];
    __syncthreads();
    const int p = permute_g(g);
    const float sc = (g < 2 * HH) ? 0.5f : 1.0f;
    #pragma unroll
    for (int vi = 0; vi < 4; vi++) {
        float s = bs[g];
        #pragma unroll
        for (int c = 0; c < CC; c++) s = fmaf(cs[vi * CC + c], ws[g * CC + c], s);
        g_xtab[(d * VV + v0 + vi) * GG + p] = s * sc;
    }
}

// ---------------------------------------------------------------------------
// Prep B (fused): w_hh fp16 permuted (r,z x0.5) + up_w transpose + proj_w fp16.
// ---------------------------------------------------------------------------
#define PREP_N0 (2 * GG * HH)
#define PREP_N1 (PREP_N0 + NLN * EE * BNK)
#define PREP_N2 (PREP_N1 + OO * EE)
__global__ void prep_misc(const float* __restrict__ whh_f,
                          const float* __restrict__ whh_b,
                          const float* __restrict__ up_w,
                          const float* __restrict__ proj_w) {
    const int i = blockIdx.x * 256 + threadIdx.x;
    if (i < PREP_N0) {
        int d = i / (GG * HH), rem = i % (GG * HH);
        int g = rem / HH, k = rem % HH;
        const float* w = d ? whh_b : whh_f;
        float v = w[g * HH + k];
        if (g < 2 * HH) v *= 0.5f;
        g_w0[d * GG * HH + permute_g(g) * HH + k] = __float2half_rn(v);
    } else if (i < PREP_N1) {
        int j = i - PREP_N0;
        int l = j / (EE * BNK), rem = j % (EE * BNK);
        int e = rem / BNK, dd = rem % BNK;
        g_upwT[(l * BNK + dd) * EE + e] = up_w[j];
    } else if (i < PREP_N2) {
        int j = i - PREP_N1;
        int o = j >> 8, e = j & 255;
        int pos = (((e >> 3) ^ (o & 7)) << 3) | (e & 7);
        g_pw16[o * EE + pos] = __float2half_rn(proj_w[j]);
    }
}

// ---------------------------------------------------------------------------
// Prep C: tokens transpose via 32x32 SMEM tiles.
// ---------------------------------------------------------------------------
__global__ void tokT_kernel(const int* __restrict__ tokens) {
    __shared__ int tile[32][33];
    const int bt = blockIdx.x, bb = blockIdx.y;
    const int x = threadIdx.x & 31, y0 = threadIdx.x >> 5;
    #pragma unroll
    for (int i = 0; i < 32; i += 8)
        tile[y0 + i][x] = tokens[(bb * 32 + y0 + i) * TT + bt * 32 + x];
    __syncthreads();
    #pragma unroll
    for (int i = 0; i < 32; i += 8)
        g_tokT[(bt * 32 + y0 + i) * BATCH + bb * 32 + x] = tile[x][y0 + i];
}

// ---------------------------------------------------------------------------
// GRU via mma: 512 threads, 2 streams x 16 rows, MERGED mma block so each B
// fragment is loaded ONCE and used by both streams (B-wavefronts halved).
// h double-buffered per stream -> one barrier per step. grid (64,2), 1 CTA/SM.
// ---------------------------------------------------------------------------
__global__ __launch_bounds__(NTH, 1) void gru_mma_kernel(
    const float* __restrict__ bhh_f, const float* __restrict__ bhh_b) {
    extern __shared__ __align__(16) char smem[];
    const uint32_t sb = (uint32_t)__cvta_generic_to_shared(smem);

    const int dir  = blockIdx.y;
    const int b0r  = blockIdx.x * BM;
    const int tid  = threadIdx.x;
    const int w    = tid >> 5;      // 0..15
    const int lane = tid & 31;
    const int lr   = lane >> 2;     // 0..7
    const int lq   = lane & 3;      // 0..3

    const float* bhh = dir ? bhh_b : bhh_f;
    const float* xt  = g_xtab + dir * VV * GG;

    // ---- load w (swizzled) ----
    {
        const uint4* gw0 = (const uint4*)(g_w0 + dir * (GG * HH));
        for (int idx = tid; idx < GG * 16; idx += NTH) {
            int n = idx >> 4, c = idx & 15;
            int off = n * 256 + ((c ^ (n & 7)) << 4);
            *(uint4*)(smem + SW0 + off) = gw0[idx];
        }
    }

    // n-gate bias (r,z folded into xtab); thread's 2 cols: j = 8w + 2lq + c
    float bias_n[2];
    #pragma unroll
    for (int c = 0; c < 2; c++)
        bias_n[c] = bhh[2 * 128 + 8 * w + 2 * lq + c];

    // ldmatrix addressing constants
    const int ar  = lane & 15;
    const int ahi = lane >> 4;
    const int asw = ar & 7;
    const int bj  = lane >> 3;
    const int bsw = lane & 7;
    const int brow = (24 * w + (lane & 7)) * 256;

    // h' store offsets (chunk index = w since unit j = 8w + ..)
    int stoff[2];
    #pragma unroll
    for (int ri = 0; ri < 2; ri++)
        stoff[ri] = (lr + 8 * ri) * 256 + ((w ^ lr) << 4) + 4 * lq;

    float hprev[2][2][2];
    #pragma unroll
    for (int s = 0; s < 2; s++)
        #pragma unroll
        for (int ri = 0; ri < 2; ri++)
            #pragma unroll
            for (int c = 0; c < 2; c++) hprev[s][ri][c] = 0.0f;

    __syncthreads();

    #pragma unroll 1
    for (int t = 0; t < TT; t++) {
        const int tcol = dir ? (TT - 1 - t) : t;
        const int* tokrow = g_tokT + tcol * BATCH + b0r;

        // xp gather for both streams (coalesced tokens, L2-resident table)
        float2 xp[2][2][3];
        #pragma unroll
        for (int s = 0; s < 2; s++)
            #pragma unroll
            for (int ri = 0; ri < 2; ri++) {
                int tok = tokrow[16 * s + 8 * ri + lr];
                const float2* xr = (const float2*)(xt + tok * GG + 24 * w);
                #pragma unroll
                for (int u = 0; u < 3; u++)
                    xp[s][ri][u] = xr[4 * u + lq];
            }

        // accumulators for both streams
        float acc[2][3][4];
        #pragma unroll
        for (int s = 0; s < 2; s++)
            #pragma unroll
            for (int rg = 0; rg < 4; rg++) {
                acc[s][0][rg] = 0.0f;
                acc[s][1][rg] = 0.0f;
                acc[s][2][rg] = bias_n[rg & 1];
            }

        // ---- merged mma: both streams share each B fragment ----
        if (t > 0) {
            const uint32_t ab0 = sb + SHB(0, t & 1) + ar * 256;
            const uint32_t ab1 = sb + SHB(1, t & 1) + ar * 256;
            #pragma unroll
            for (int kc2 = 0; kc2 < 4; kc2++) {
                uint32_t a0[8], a1[8];
                uint32_t clo = (uint32_t)(((4 * kc2 + ahi) ^ asw) << 4);
                uint32_t chi = (uint32_t)(((4 * kc2 + 2 + ahi) ^ asw) << 4);
                ldsm4(a0[0], a0[1], a0[2], a0[3], ab0 + clo);
                ldsm4(a0[4], a0[5], a0[6], a0[7], ab0 + chi);
                ldsm4(a1[0], a1[1], a1[2], a1[3], ab1 + clo);
                ldsm4(a1[4], a1[5], a1[6], a1[7], ab1 + chi);
                const uint32_t chunk = (uint32_t)(((4 * kc2 + bj) ^ bsw) << 4);
                #pragma unroll
                for (int nt = 0; nt < 3; nt++) {
                    uint32_t bh[4];
                    ldsm4(bh[0], bh[1], bh[2], bh[3],
                          sb + SW0 + brow + nt * 2048 + chunk);
                    mma16816(acc[0][nt], a0 + 0, bh[0], bh[1]);
                    mma16816(acc[0][nt], a0 + 4, bh[2], bh[3]);
                    mma16816(acc[1][nt], a1 + 0, bh[0], bh[1]);
                    mma16816(acc[1][nt], a1 + 4, bh[2], bh[3]);
                }
            }
        }

        // ---- gates (both streams): packed f16x2 r,z; n via tanh_e ----
        #pragma unroll
        for (int s = 0; s < 2; s++) {
            const uint32_t wrb_off = (uint32_t)SHB(s, (t + 1) & 1);
            #pragma unroll
            for (int ri = 0; ri < 2; ri++) {
                float xr0 = xp[s][ri][0].x + acc[s][0][2 * ri + 0];
                float xr1 = xp[s][ri][0].y + acc[s][0][2 * ri + 1];
                float xz0 = xp[s][ri][1].x + acc[s][1][2 * ri + 0];
                float xz1 = xp[s][ri][1].y + acc[s][1][2 * ri + 1];
                uint32_t xr2, xz2, tr2, tz2;
                asm("cvt.rn.f16x2.f32 %0, %1, %2;" : "=r"(xr2) : "f"(xr1), "f"(xr0));
                asm("cvt.rn.f16x2.f32 %0, %1, %2;" : "=r"(xz2) : "f"(xz1), "f"(xz0));
                asm("tanh.approx.f16x2 %0, %1;" : "=r"(tr2) : "r"(xr2));
                asm("tanh.approx.f16x2 %0, %1;" : "=r"(tz2) : "r"(xz2));
                __half2 trh = *reinterpret_cast<__half2*>(&tr2);
                __half2 tzh = *reinterpret_cast<__half2*>(&tz2);
                float r0 = fmaf(__low2float(trh),  0.5f, 0.5f);
                float r1 = fmaf(__high2float(trh), 0.5f, 0.5f);
                float z0 = fmaf(__low2float(tzh),  0.5f, 0.5f);
                float z1 = fmaf(__high2float(tzh), 0.5f, 0.5f);
                float n0 = tanh_e(fmaf(r0, acc[s][2][2 * ri + 0], xp[s][ri][2].x));
                float n1 = tanh_e(fmaf(r1, acc[s][2][2 * ri + 1], xp[s][ri][2].y));
                float h0 = fmaf(z0, hprev[s][ri][0] - n0, n0);
                float h1 = fmaf(z1, hprev[s][ri][1] - n1, n1);
                hprev[s][ri][0] = h0;
                hprev[s][ri][1] = h1;
                uint32_t hpk;
                asm("cvt.rn.f16x2.f32 %0, %1, %2;" : "=r"(hpk) : "f"(h1), "f"(h0));
                *(uint32_t*)(smem + wrb_off + stoff[ri]) = hpk;
            }
        }
        __syncthreads();
    }

    // final hidden -> feat
    #pragma unroll
    for (int s = 0; s < 2; s++)
        #pragma unroll
        for (int ri = 0; ri < 2; ri++)
            #pragma unroll
            for (int c = 0; c < 2; c++) {
                int m = 16 * s + lr + 8 * ri;
                int j = 8 * w + 2 * lq + c;
                g_feat[(b0r + m) * EE + dir * HH + j] = hprev[s][ri][c];
            }
}

// ---------------------------------------------------------------------------
// Head v6 (R12-exact): HB=16 rows, 512 threads, grid 128 (single wave).
// ---------------------------------------------------------------------------
#define HB 16
__global__ __launch_bounds__(512) void head_kernel(
    const int* __restrict__ lang_ids,
    const float* __restrict__ down_w, const float* __restrict__ down_b,
    const float* __restrict__ up_b,
    const float* __restrict__ ln_g,   const float* __restrict__ ln_b,
    const float* __restrict__ proj_b,
    float* __restrict__ out) {
    extern __shared__ __align__(16) char hsm[];
    const uint32_t sb = (uint32_t)__cvta_generic_to_shared(hsm);
    const int tid = threadIdx.x, w = tid >> 5, lane = tid & 31;
    const int b0 = blockIdx.x * HB;
    const int b = b0 + w;
    const int l = lang_ids[b];
    const float* fb = g_feat + b * EE;

    // ---- stage adapter weights (all langs) into SMEM ----
    {
        const uint4* gd = (const uint4*)down_w;
        const uint4* gu = (const uint4*)g_upwT;
        #pragma unroll
        for (int k = 0; k < 12; k++) {
            ((uint4*)(hsm + HDOWN))[tid + 512 * k] = gd[tid + 512 * k];
            ((uint4*)(hsm + HUP))[tid + 512 * k]   = gu[tid + 512 * k];
        }
    }
    __syncthreads();

    // ---- adapter (one row per warp), weights from SMEM ----
    float4 f4[8];
    #pragma unroll
    for (int c = 0; c < 8; c++)
        f4[c] = *(const float4*)(fb + (lane & 7) * 4 + 32 * c);

    float hid = 0.0f;
    const float* dwb = (const float*)(hsm + HDOWN) + l * BNK * EE;
    #pragma unroll
    for (int g = 0; g < 8; g++) {
        const int d = 4 * g + (lane >> 3);
        const float* wr = dwb + d * EE + (lane & 7) * 4;
        float s = 0.0f;
        #pragma unroll
        for (int c = 0; c < 8; c++) {
            float4 wv = *(const float4*)(wr + 32 * c);
            s = fmaf(f4[c].x, wv.x, s); s = fmaf(f4[c].y, wv.y, s);
            s = fmaf(f4[c].z, wv.z, s); s = fmaf(f4[c].w, wv.w, s);
        }
        s += __shfl_xor_sync(0xffffffffu, s, 1);
        s += __shfl_xor_sync(0xffffffffu, s, 2);
        s += __shfl_xor_sync(0xffffffffu, s, 4);
        float got = __shfl_sync(0xffffffffu, s, (lane & 3) * 8);
        if ((lane >> 2) == g) hid = got;
    }
    hid += down_b[l * BNK + lane];
    hid = 0.5f * hid * (1.0f + erff(hid * 0.7071067811865476f));

    const float4 fx0 = *(const float4*)(fb + lane * 8);
    const float4 fx1 = *(const float4*)(fb + lane * 8 + 4);
    float4 a0 = *(const float4*)(up_b + l * EE + lane * 8);
    float4 a1 = *(const float4*)(up_b + l * EE + lane * 8 + 4);
    const float* uwb = (const float*)(hsm + HUP) + l * BNK * EE;
    #pragma unroll 4
    for (int d = 0; d < BNK; d++) {
        float hd = __shfl_sync(0xffffffffu, hid, d);
        float4 u0 = *(const float4*)(uwb + d * EE + lane * 8);
        float4 u1 = *(const float4*)(uwb + d * EE + lane * 8 + 4);
        a0.x = fmaf(hd, u0.x, a0.x); a0.y = fmaf(hd, u0.y, a0.y);
        a0.z = fmaf(hd, u0.z, a0.z); a0.w = fmaf(hd, u0.w, a0.w);
        a1.x = fmaf(hd, u1.x, a1.x); a1.y = fmaf(hd, u1.y, a1.y);
        a1.z = fmaf(hd, u1.z, a1.z); a1.w = fmaf(hd, u1.w, a1.w);
    }
    float x[8] = {fx0.x + a0.x, fx0.y + a0.y, fx0.z + a0.z, fx0.w + a0.w,
                  fx1.x + a1.x, fx1.y + a1.y, fx1.z + a1.z, fx1.w + a1.w};
    float s1 = 0.0f, s2 = 0.0f;
    #pragma unroll
    for (int j = 0; j < 8; j++) { s1 += x[j]; s2 = fmaf(x[j], x[j], s2); }
    #pragma unroll
    for (int o = 16; o; o >>= 1) {
        s1 += __shfl_xor_sync(0xffffffffu, s1, o);
        s2 += __shfl_xor_sync(0xffffffffu, s2, o);
    }
    const float mu = s1 * (1.0f / EE);
    const float rstd = rsqrtf(s2 * (1.0f / EE) - mu * mu + 1e-5f);
    const float4 g0 = *(const float4*)(ln_g + l * EE + lane * 8);
    const float4 g1 = *(const float4*)(ln_g + l * EE + lane * 8 + 4);
    const float4 bb0 = *(const float4*)(ln_b + l * EE + lane * 8);
    const float4 bb1 = *(const float4*)(ln_b + l * EE + lane * 8 + 4);
    float y[8];
    y[0] = (x[0]-mu)*rstd*g0.x + bb0.x;  y[1] = (x[1]-mu)*rstd*g0.y + bb0.y;
    y[2] = (x[2]-mu)*rstd*g0.z + bb0.z;  y[3] = (x[3]-mu)*rstd*g0.w + bb0.w;
    y[4] = (x[4]-mu)*rstd*g1.x + bb1.x;  y[5] = (x[5]-mu)*rstd*g1.y + bb1.y;
    y[6] = (x[6]-mu)*rstd*g1.z + bb1.z;  y[7] = (x[7]-mu)*rstd*g1.w + bb1.w;

    {
        __half h_[8], c_[8];
        #pragma unroll
        for (int j = 0; j < 8; j++) {
            h_[j] = __float2half_rn(y[j]);
            c_[j] = __float2half_rn(y[j] - __half2float(h_[j]));
        }
        const int off = w * 512 + ((lane ^ (w & 7)) << 4);
        *(uint4*)(hsm + HYHI + off) = *(const uint4*)h_;
        *(uint4*)(hsm + HYLO + off) = *(const uint4*)c_;
    }
    __syncthreads();

    // ---- phase B: reuse weight region for proj_w fp16, then mma ----
    {
        const uint4* gp = (const uint4*)g_pw16;
        #pragma unroll
        for (int k = 0; k < 16; k++)
            ((uint4*)(hsm + HDOWN))[tid + 512 * k] = gp[tid + 512 * k];
    }
    __syncthreads();

    const int ar  = lane & 15;
    const int ahi = lane >> 4;
    const int asw = ar & 7;
    const int bj  = lane >> 3;
    const int bsw = lane & 7;
    const uint32_t ahib = sb + HYHI + ar * 512;
    const uint32_t alob = sb + HYLO + ar * 512;
    const uint32_t brow0 = sb + HDOWN + (16 * w + (lane & 7)) * 512;
    const uint32_t brow1 = brow0 + 8 * 512;

    const int lr = lane >> 2, lq = lane & 3;
    float pb0 = proj_b[16 * w + 2 * lq];
    float pb1 = proj_b[16 * w + 2 * lq + 1];
    float pb8 = proj_b[16 * w + 8 + 2 * lq];
    float pb9 = proj_b[16 * w + 8 + 2 * lq + 1];
    float acc[2][4] = {{pb0, pb1, pb0, pb1}, {pb8, pb9, pb8, pb9}};

    #pragma unroll
    for (int kc32 = 0; kc32 < 8; kc32++) {
        uint32_t ah[8], al[8], bF0[4], bF1[4];
        uint32_t clo = (uint32_t)(((4 * kc32 + ahi) ^ asw) << 4);
        uint32_t chi = (uint32_t)(((4 * kc32 + 2 + ahi) ^ asw) << 4);
        ldsm4(ah[0], ah[1], ah[2], ah[3], ahib + clo);
        ldsm4(ah[4], ah[5], ah[6], ah[7], ahib + chi);
        ldsm4(al[0], al[1], al[2], al[3], alob + clo);
        ldsm4(al[4], al[5], al[6], al[7], alob + chi);
        uint32_t bc = (uint32_t)(((4 * kc32 + bj) ^ bsw) << 4);
        ldsm4(bF0[0], bF0[1], bF0[2], bF0[3], brow0 + bc);
        ldsm4(bF1[0], bF1[1], bF1[2], bF1[3], brow1 + bc);
        #pragma unroll
        for (int kk = 0; kk < 2; kk++) {
            mma16816(acc[0], ah + 4 * kk, bF0[2 * kk], bF0[2 * kk + 1]);
            mma16816(acc[0], al + 4 * kk, bF0[2 * kk], bF0[2 * kk + 1]);
            mma16816(acc[1], ah + 4 * kk, bF1[2 * kk], bF1[2 * kk + 1]);
            mma16816(acc[1], al + 4 * kk, bF1[2 * kk], bF1[2 * kk + 1]);
        }
    }

    #pragma unroll
    for (int nt = 0; nt < 2; nt++) {
        const int col = 16 * w + 8 * nt + 2 * lq;
        *(float2*)(out + (b0 + lr) * OO + col)
            = make_float2(acc[nt][0], acc[nt][1]);
        *(float2*)(out + (b0 + lr + 8) * OO + col)
            = make_float2(acc[nt][2], acc[nt][3]);
    }
}

// ---------------------------------------------------------------------------
extern "C" void kernel_launch(void* const* d_in, const int* in_sizes, int n_in,
                              void* d_out, int out_size) {
    const int*   tokens = (const int*)d_in[0];
    const int*   lang   = (const int*)d_in[1];
    const float* ce     = (const float*)d_in[2];
    const float* wih_f  = (const float*)d_in[3];
    const float* whh_f  = (const float*)d_in[4];
    const float* bih_f  = (const float*)d_in[5];
    const float* bhh_f  = (const float*)d_in[6];
    const float* wih_b  = (const float*)d_in[7];
    const float* whh_b  = (const float*)d_in[8];
    const float* bih_b  = (const float*)d_in[9];
    const float* bhh_b  = (const float*)d_in[10];
    const float* down_w = (const float*)d_in[11];
    const float* down_b = (const float*)d_in[12];
    const float* up_w   = (const float*)d_in[13];
    const float* up_b   = (const float*)d_in[14];
    const float* ln_g   = (const float*)d_in[15];
    const float* ln_b   = (const float*)d_in[16];
    const float* proj_w = (const float*)d_in[17];
    const float* proj_b = (const float*)d_in[18];
    float* out = (float*)d_out;

    cudaFuncSetAttribute(gru_mma_kernel,
                         cudaFuncAttributeMaxDynamicSharedMemorySize, SMEM_TOTAL);
    cudaFuncSetAttribute(head_kernel,
                         cudaFuncAttributeMaxDynamicSharedMemorySize, HEAD_SMEM);
    const size_t xsmem = (size_t)(GG * CC + GG + 4 * CC) * sizeof(float);
    cudaFuncSetAttribute(xtab_kernel,
                         cudaFuncAttributeMaxDynamicSharedMemorySize, (int)xsmem);

    tokT_kernel<<<dim3(TT / 32, BATCH / 32), 256>>>(tokens);
    prep_misc<<<(PREP_N2 + 255) / 256, 256>>>(whh_f, whh_b, up_w, proj_w);
    xtab_kernel<<<dim3(VV / 4, 2), GG, xsmem>>>(ce, wih_f, bih_f, wih_b, bih_b,
                                                bhh_f, bhh_b);
    gru_mma_kernel<<<dim3(BATCH / BM, 2), NTH, SMEM_TOTAL>>>(bhh_f, bhh_b);
    head_kernel<<<BATCH / HB, 512, HEAD_SMEM>>>(lang, down_w, down_b, up_b,
                                                ln_g, ln_b, proj_b, out);
}